// round 3
// baseline (speedup 1.0000x reference)
#include <cuda_runtime.h>

// Soft-argmax: input (B=4, C=14, H=1024, W=1024) fp32 NCHW.
// Channels split into OUT_CHANNELS=2 groups of K=7; per-pixel softmax over K,
// weighted sum with w_k = (k-3)*1.0. Output (4, 2, 1024, 1024) fp32.
//
// R3: thread coarsening x2 — each thread processes 2 quads (blockDim-strided,
// all LDG.128 fully coalesced), 28 front-batched streaming loads per thread.

#define HW      (1024 * 1024)
#define HWQ     (HW / 4)          // 262144 = 2^18 quads per plane
#define HWQ_LOG 18
#define C_IN    14
#define B       4
#define QPT     2                 // quads per thread

__device__ __forceinline__ float soft1(float a0, float a1, float a2, float a3,
                                       float a4, float a5, float a6) {
    float e0 = __expf(a0);
    float e1 = __expf(a1);
    float e2 = __expf(a2);
    float e3 = __expf(a3);
    float e4 = __expf(a4);
    float e5 = __expf(a5);
    float e6 = __expf(a6);
    float den = ((e0 + e1) + (e2 + e3)) + ((e4 + e5) + e6);
    float pos = fmaf(3.0f, e6, fmaf(2.0f, e5, e4));
    float neg = fmaf(3.0f, e0, fmaf(2.0f, e1, e2));
    return __fdividef(pos - neg, den);
}

__global__ __launch_bounds__(256, 1)
void softargmax_kernel(const float4* __restrict__ x, float4* __restrict__ out) {
    // Each block covers QPT*blockDim consecutive quads of the flat [0, B*HWQ) space.
    int base = blockIdx.x * (QPT * 256) + threadIdx.x;

    float4 v[QPT][C_IN];

    // Front-batch all 28 loads (each instruction fully coalesced across the warp).
#pragma unroll
    for (int j = 0; j < QPT; j++) {
        int q = base + j * 256;
        int b = q >> HWQ_LOG;
        int s = q & (HWQ - 1);
        const float4* in = x + (size_t)b * C_IN * HWQ + s;
#pragma unroll
        for (int c = 0; c < C_IN; c++) {
            v[j][c] = __ldcs(&in[(size_t)c * HWQ]);
        }
    }

#pragma unroll
    for (int j = 0; j < QPT; j++) {
        const float* f = reinterpret_cast<const float*>(v[j]);  // f[c*4 + lane]

        float4 r0, r1;
        float* o0 = reinterpret_cast<float*>(&r0);
        float* o1 = reinterpret_cast<float*>(&r1);

#pragma unroll
        for (int l = 0; l < 4; l++) {
            o0[l] = soft1(f[0*4+l], f[1*4+l], f[2*4+l], f[3*4+l],
                          f[4*4+l], f[5*4+l], f[6*4+l]);
            o1[l] = soft1(f[7*4+l], f[8*4+l], f[9*4+l], f[10*4+l],
                          f[11*4+l], f[12*4+l], f[13*4+l]);
        }

        int q = base + j * 256;
        int b = q >> HWQ_LOG;
        int s = q & (HWQ - 1);
        float4* ob = out + (size_t)b * 2 * HWQ + s;
        __stcs(&ob[0],   r0);
        __stcs(&ob[HWQ], r1);
    }
}

extern "C" void kernel_launch(void* const* d_in, const int* in_sizes, int n_in,
                              void* d_out, int out_size) {
    const float4* x = (const float4*)d_in[0];
    float4* out = (float4*)d_out;

    const int total_quads = B * HWQ;                    // 1,048,576
    const int threads = 256;
    const int blocks = total_quads / (threads * QPT);   // 2048

    softargmax_kernel<<<blocks, threads>>>(x, out);
}